// round 4
// baseline (speedup 1.0000x reference)
#include <cuda_runtime.h>
#include <cuda_fp16.h>
#include <cuda_bf16.h>

// ---------------------------------------------------------------------------
// PhysicsConvolution: X0 = notes@w ; X1 = segment_sum(ew * X0[dst], src) ;
// out = concat(relu(X1 + b), X0[garment:])
//
// CSR build runs on a side stream concurrently with the GEMM (event
// fork/join, graph-capture legal); gather joins both. X0 stored fp16
// (gather-only consumer); out-tail written fp32 from GEMM accumulators.
// ---------------------------------------------------------------------------

#define HD 128
#define BM 64

#define MAXN 131072
#define MAXE 1700000
#define SCAN_BLK 1024

__device__ uint2 g_X0h[3400000];        // fp16 X0: [N][32] x 4 halves
__device__ int2  g_sdw[MAXE];           // CSR payload {dst, w}
__device__ int   g_cnt[MAXN + 1];       // zero at load; scan1 restores zeros
__device__ int   g_off[MAXN + 2];
__device__ int   g_cur[MAXN + 1];
__device__ int   g_blk[256];

// side stream + fork/join events (host objects; created pre-main, no device mem)
static cudaStream_t g_s1;
static cudaEvent_t  g_e0, g_e1;
namespace {
struct StreamInit {
    StreamInit() {
        cudaStreamCreateWithFlags(&g_s1, cudaStreamNonBlocking);
        cudaEventCreateWithFlags(&g_e0, cudaEventDisableTiming);
        cudaEventCreateWithFlags(&g_e1, cudaEventDisableTiming);
    }
};
StreamInit g_stream_init;
}

// ---------------------------------------------------------------------------
// GEMM: X0 = A[N,128] @ W[128,128]; fp16 X0 store, fp32 out-tail.
// ---------------------------------------------------------------------------
__global__ __launch_bounds__(256) void gemm_kernel(
    const float4* __restrict__ A4,
    const float4* __restrict__ W4,
    float4* __restrict__ out4,
    int N, int g)
{
    __shared__ float4 sA[BM * 32];
    __shared__ float4 sB[HD * 32];

    const int tid  = threadIdx.x;
    const int row0 = blockIdx.x * BM;

    #pragma unroll
    for (int i = tid; i < HD * 32; i += 256) sB[i] = W4[i];
    for (int i = tid; i < BM * 32; i += 256) {
        int r = row0 + (i >> 5);
        sA[i] = (r < N) ? A4[(size_t)r * 32 + (i & 31)]
                        : make_float4(0.f, 0.f, 0.f, 0.f);
    }
    __syncthreads();

    const int tx = tid & 31;
    const int ty = tid >> 5;

    float4 acc[8];
    #pragma unroll
    for (int i = 0; i < 8; i++) acc[i] = make_float4(0.f, 0.f, 0.f, 0.f);

    #pragma unroll 4
    for (int k4 = 0; k4 < 32; k4++) {
        float4 b0 = sB[(k4 * 4 + 0) * 32 + tx];
        float4 b1 = sB[(k4 * 4 + 1) * 32 + tx];
        float4 b2 = sB[(k4 * 4 + 2) * 32 + tx];
        float4 b3 = sB[(k4 * 4 + 3) * 32 + tx];
        #pragma unroll
        for (int i = 0; i < 8; i++) {
            float4 a = sA[(ty * 8 + i) * 32 + k4];
            acc[i].x += a.x * b0.x + a.y * b1.x + a.z * b2.x + a.w * b3.x;
            acc[i].y += a.x * b0.y + a.y * b1.y + a.z * b2.y + a.w * b3.y;
            acc[i].z += a.x * b0.z + a.y * b1.z + a.z * b2.z + a.w * b3.z;
            acc[i].w += a.x * b0.w + a.y * b1.w + a.z * b2.w + a.w * b3.w;
        }
    }

    #pragma unroll
    for (int i = 0; i < 8; i++) {
        int r = row0 + ty * 8 + i;
        if (r < N) {
            __half2 lo = __float22half2_rn(make_float2(acc[i].x, acc[i].y));
            __half2 hi = __float22half2_rn(make_float2(acc[i].z, acc[i].w));
            uint2 p;
            p.x = *reinterpret_cast<unsigned*>(&lo);
            p.y = *reinterpret_cast<unsigned*>(&hi);
            g_X0h[(size_t)r * 32 + tx] = p;
            if (r >= g)
                out4[(size_t)(N + r - g) * 32 + tx] = acc[i];
        }
    }
}

// ---------------------------------------------------------------------------
// CSR build
// ---------------------------------------------------------------------------
__global__ void hist_kernel(const int* __restrict__ esrc, int E) {
    for (int e = blockIdx.x * blockDim.x + threadIdx.x; e < E;
         e += gridDim.x * blockDim.x)
        atomicAdd(&g_cnt[esrc[e]], 1);
}

// scan1: block-local exclusive scan of counts (re-zeroes g_cnt) + block total.
__global__ __launch_bounds__(256) void scan1_kernel(int N) {
    __shared__ int ssum[256];
    const int t = threadIdx.x;
    const int base = blockIdx.x * SCAN_BLK + t * 4;

    int c0 = 0, c1 = 0, c2 = 0, c3 = 0;
    if (base + 0 < N) { c0 = g_cnt[base + 0]; g_cnt[base + 0] = 0; }
    if (base + 1 < N) { c1 = g_cnt[base + 1]; g_cnt[base + 1] = 0; }
    if (base + 2 < N) { c2 = g_cnt[base + 2]; g_cnt[base + 2] = 0; }
    if (base + 3 < N) { c3 = g_cnt[base + 3]; g_cnt[base + 3] = 0; }
    int tot = c0 + c1 + c2 + c3;

    ssum[t] = tot;
    __syncthreads();
    #pragma unroll
    for (int off = 1; off < 256; off <<= 1) {
        int v = (t >= off) ? ssum[t - off] : 0;
        __syncthreads();
        ssum[t] += v;
        __syncthreads();
    }
    int ex = ssum[t] - tot;

    if (base + 0 < N) g_off[base + 0] = ex;
    if (base + 1 < N) g_off[base + 1] = ex + c0;
    if (base + 2 < N) g_off[base + 2] = ex + c0 + c1;
    if (base + 3 < N) g_off[base + 3] = ex + c0 + c1 + c2;
    if (t == 255) g_blk[blockIdx.x] = ssum[255];
}

// scan3: every block scans the (<=256) block totals itself, adds its block
// offset, inits cursors, sets sentinel.  (scan2 eliminated.)
__global__ __launch_bounds__(256) void scan3_kernel(int N, int E, int NB) {
    __shared__ int ssum[256];
    __shared__ int s_off;
    const int t = threadIdx.x;

    int v0 = (t < NB) ? g_blk[t] : 0;
    ssum[t] = v0;
    __syncthreads();
    #pragma unroll
    for (int off = 1; off < 256; off <<= 1) {
        int v = (t >= off) ? ssum[t - off] : 0;
        __syncthreads();
        ssum[t] += v;
        __syncthreads();
    }
    if (t == blockIdx.x) s_off = ssum[t] - v0;   // exclusive prefix for this block
    __syncthreads();

    const int boff = s_off;
    const int base = blockIdx.x * SCAN_BLK + t * 4;
    #pragma unroll
    for (int u = 0; u < 4; u++) {
        int i = base + u;
        if (i < N) {
            int v = g_off[i] + boff;
            g_off[i] = v;
            g_cur[i] = v;
        }
    }
    if (blockIdx.x == 0 && t == 0) g_off[N] = E;
}

__global__ void scatter_kernel(const int* __restrict__ esrc,
                               const int* __restrict__ edst,
                               const float* __restrict__ ew, int E) {
    for (int e = blockIdx.x * blockDim.x + threadIdx.x; e < E;
         e += gridDim.x * blockDim.x) {
        int s = esrc[e];
        int p = atomicAdd(&g_cur[s], 1);
        g_sdw[p] = make_int2(edst[e], __float_as_int(ew[e]));
    }
}

// ---------------------------------------------------------------------------
// Gather: warp per node; edge descriptors via uniform broadcast loads
// (no shuffles). fp32 accumulate, fused bias+relu -> out head.
// ---------------------------------------------------------------------------
__global__ __launch_bounds__(256) void gather_kernel(
    const float4* __restrict__ b4,
    float4* __restrict__ out4,
    int N)
{
    const int lane = threadIdx.x & 31;
    const int node = (blockIdx.x * blockDim.x + threadIdx.x) >> 5;
    if (node >= N) return;

    const int start = g_off[node];
    const int end   = g_off[node + 1];

    float4 acc = make_float4(0.f, 0.f, 0.f, 0.f);

    int k = start;
    for (; k + 4 <= end; k += 4) {
        int2 p0 = __ldg(&g_sdw[k + 0]);      // uniform across warp: broadcast
        int2 p1 = __ldg(&g_sdw[k + 1]);
        int2 p2 = __ldg(&g_sdw[k + 2]);
        int2 p3 = __ldg(&g_sdw[k + 3]);
        uint2 u0 = g_X0h[(size_t)p0.x * 32 + lane];
        uint2 u1 = g_X0h[(size_t)p1.x * 32 + lane];
        uint2 u2 = g_X0h[(size_t)p2.x * 32 + lane];
        uint2 u3 = g_X0h[(size_t)p3.x * 32 + lane];
        float w0 = __int_as_float(p0.y);
        float w1 = __int_as_float(p1.y);
        float w2 = __int_as_float(p2.y);
        float w3 = __int_as_float(p3.y);
        float2 a0 = __half22float2(*reinterpret_cast<__half2*>(&u0.x));
        float2 c0 = __half22float2(*reinterpret_cast<__half2*>(&u0.y));
        float2 a1 = __half22float2(*reinterpret_cast<__half2*>(&u1.x));
        float2 c1 = __half22float2(*reinterpret_cast<__half2*>(&u1.y));
        float2 a2 = __half22float2(*reinterpret_cast<__half2*>(&u2.x));
        float2 c2 = __half22float2(*reinterpret_cast<__half2*>(&u2.y));
        float2 a3 = __half22float2(*reinterpret_cast<__half2*>(&u3.x));
        float2 c3 = __half22float2(*reinterpret_cast<__half2*>(&u3.y));
        acc.x += w0 * a0.x + w1 * a1.x + w2 * a2.x + w3 * a3.x;
        acc.y += w0 * a0.y + w1 * a1.y + w2 * a2.y + w3 * a3.y;
        acc.z += w0 * c0.x + w1 * c1.x + w2 * c2.x + w3 * c3.x;
        acc.w += w0 * c0.y + w1 * c1.y + w2 * c2.y + w3 * c3.y;
    }
    for (; k < end; k++) {
        int2 p = __ldg(&g_sdw[k]);
        float w = __int_as_float(p.y);
        uint2 u = g_X0h[(size_t)p.x * 32 + lane];
        float2 a = __half22float2(*reinterpret_cast<__half2*>(&u.x));
        float2 c = __half22float2(*reinterpret_cast<__half2*>(&u.y));
        acc.x += w * a.x;
        acc.y += w * a.y;
        acc.z += w * c.x;
        acc.w += w * c.y;
    }

    float4 bb = __ldg(b4 + lane);
    acc.x = fmaxf(acc.x + bb.x, 0.f);
    acc.y = fmaxf(acc.y + bb.y, 0.f);
    acc.z = fmaxf(acc.z + bb.z, 0.f);
    acc.w = fmaxf(acc.w + bb.w, 0.f);
    out4[(size_t)node * 32 + lane] = acc;
}

// ---------------------------------------------------------------------------
extern "C" void kernel_launch(void* const* d_in, const int* in_sizes, int n_in,
                              void* d_out, int out_size)
{
    const float* notes = (const float*)d_in[0];
    const float* w     = (const float*)d_in[1];
    const float* b     = (const float*)d_in[2];
    const int*   esrc  = (const int*)  d_in[3];
    const int*   edst  = (const int*)  d_in[4];
    const float* ew    = (const float*)d_in[5];

    const int H = in_sizes[2];
    const int D = in_sizes[1] / H;
    const int N = in_sizes[0] / D;
    const int E = in_sizes[3];
    const int g = 2 * N - out_size / H;

    float4* out4 = (float4*)d_out;
    const int NB = (N + SCAN_BLK - 1) / SCAN_BLK;

    // fork: side stream runs the CSR chain concurrently with the GEMM
    cudaEventRecord(g_e0, 0);
    cudaStreamWaitEvent(g_s1, g_e0, 0);

    gemm_kernel<<<(N + BM - 1) / BM, 256, 0, 0>>>(
        (const float4*)notes, (const float4*)w, out4, N, g);

    hist_kernel<<<592, 256, 0, g_s1>>>(esrc, E);
    scan1_kernel<<<NB, 256, 0, g_s1>>>(N);
    scan3_kernel<<<NB, 256, 0, g_s1>>>(N, E, NB);
    scatter_kernel<<<592, 256, 0, g_s1>>>(esrc, edst, ew, E);

    // join
    cudaEventRecord(g_e1, g_s1);
    cudaStreamWaitEvent(0, g_e1, 0);

    gather_kernel<<<(N * 32 + 255) / 256, 256, 0, 0>>>(
        (const float4*)b, out4, N);
}

// round 5
// speedup vs baseline: 1.0127x; 1.0127x over previous
#include <cuda_runtime.h>
#include <cuda_fp16.h>
#include <cuda_bf16.h>
#include <mma.h>

using namespace nvcuda;

// ---------------------------------------------------------------------------
// PhysicsConvolution: X0 = notes@w ; X1 = segment_sum(ew * X0[dst], src) ;
// out = concat(relu(X1 + b), X0[garment:])
//
// R5 = R3 kernel (206.9us) + ONE change: fp16 split-precision HMMA GEMM
// (X0 = Ah@Wh + Ah@Wl + Al@Wh, fp32 accum -> ~fp32-accurate X0).
// ---------------------------------------------------------------------------

#define HD 128
#define BM 64

#define MAXN 131072
#define MAXE 1700000
#define SCAN_BLK 1024

__device__ uint2  g_X0h[3400000];       // fp16 X0: [N][32] x 4 halves
__device__ int2   g_sdw[MAXE];          // CSR payload {dst, w}
__device__ int    g_cnt[MAXN + 1];      // zero at load; scan1 restores zeros
__device__ int    g_off[MAXN + 2];
__device__ int    g_cur[MAXN + 1];
__device__ int    g_blk[256];
__device__ __half g_Wh[HD * HD];        // W split: hi fp16
__device__ __half g_Wl[HD * HD];        // W split: lo residual fp16

// ---------------------------------------------------------------------------
// W split prep: Wh = fp16(w), Wl = fp16(w - Wh).  One small block.
// ---------------------------------------------------------------------------
__global__ void wprep_kernel(const float* __restrict__ w) {
    for (int i = threadIdx.x; i < HD * HD; i += blockDim.x) {
        float  v  = w[i];
        __half hi = __float2half_rn(v);
        __half lo = __float2half_rn(v - __half2float(hi));
        g_Wh[i] = hi;
        g_Wl[i] = lo;
    }
}

// ---------------------------------------------------------------------------
// GEMM via split-fp16 HMMA.  Block: 256 thr = 8 warps, 64 rows x 128 cols.
// Warp (wr = wid/2, wc = wid%2) computes rows wr*16..+15, cols wc*64..+63
// as 4 wmma 16x16x16 accumulators.  A tile converted fp32->(hi,lo) fp16 in
// smem; W fragments read from L1-resident __device__ arrays.  Epilogue
// stages fp32 C through the same smem, then packs fp16 X0 + fp32 tail.
// ---------------------------------------------------------------------------
__global__ __launch_bounds__(256) void gemm_kernel(
    const float4* __restrict__ A4,
    float4* __restrict__ out4,
    int N, int g)
{
    __shared__ float sC[BM * HD];                         // 32 KB
    __half* sAh = reinterpret_cast<__half*>(sC);          // alias: A hi
    __half* sAl = reinterpret_cast<__half*>(sC) + BM * HD;// alias: A lo

    const int tid  = threadIdx.x;
    const int row0 = blockIdx.x * BM;

    // Load A tile (fp32) and split into (hi, lo) fp16 in smem.
    #pragma unroll
    for (int i = tid; i < BM * 32; i += 256) {
        int r = row0 + (i >> 5);
        float4 a = (r < N) ? A4[(size_t)r * 32 + (i & 31)]
                           : make_float4(0.f, 0.f, 0.f, 0.f);
        int base = (i >> 5) * HD + (i & 31) * 4;
        #pragma unroll
        for (int u = 0; u < 4; u++) {
            float  v  = (&a.x)[u];
            __half hi = __float2half_rn(v);
            sAh[base + u] = hi;
            sAl[base + u] = __float2half_rn(v - __half2float(hi));
        }
    }
    __syncthreads();

    const int wid = tid >> 5;
    const int wr  = wid >> 1;          // row group 0..3 -> rows wr*16
    const int wc  = wid & 1;           // col group 0..1 -> cols wc*64

    wmma::fragment<wmma::accumulator, 16, 16, 16, float> acc[4];
    #pragma unroll
    for (int j = 0; j < 4; j++) wmma::fill_fragment(acc[j], 0.f);

    #pragma unroll
    for (int k = 0; k < 8; k++) {
        const int k0 = k * 16;
        wmma::fragment<wmma::matrix_a, 16, 16, 16, __half, wmma::row_major> ah, al;
        wmma::load_matrix_sync(ah, sAh + (wr * 16) * HD + k0, HD);
        wmma::load_matrix_sync(al, sAl + (wr * 16) * HD + k0, HD);
        #pragma unroll
        for (int j = 0; j < 4; j++) {
            const int col = wc * 64 + j * 16;
            wmma::fragment<wmma::matrix_b, 16, 16, 16, __half, wmma::row_major> bh, bl;
            wmma::load_matrix_sync(bh, g_Wh + k0 * HD + col, HD);
            wmma::load_matrix_sync(bl, g_Wl + k0 * HD + col, HD);
            wmma::mma_sync(acc[j], ah, bh, acc[j]);
            wmma::mma_sync(acc[j], ah, bl, acc[j]);
            wmma::mma_sync(acc[j], al, bh, acc[j]);
        }
    }

    __syncthreads();   // all warps done reading A from smem
    #pragma unroll
    for (int j = 0; j < 4; j++)
        wmma::store_matrix_sync(sC + (wr * 16) * HD + wc * 64 + j * 16,
                                acc[j], HD, wmma::mem_row_major);
    __syncthreads();

    // Pack: fp16 X0 for gather, fp32 tail rows for out.
    const int tx = tid & 31;    // col-f4 0..31
    const int ty = tid >> 5;    // 8 rows each
    #pragma unroll
    for (int i = 0; i < 8; i++) {
        int rl = ty * 8 + i;
        int r  = row0 + rl;
        if (r < N) {
            float4 v = *reinterpret_cast<float4*>(sC + rl * HD + tx * 4);
            __half2 lo = __float22half2_rn(make_float2(v.x, v.y));
            __half2 hi = __float22half2_rn(make_float2(v.z, v.w));
            uint2 p;
            p.x = *reinterpret_cast<unsigned*>(&lo);
            p.y = *reinterpret_cast<unsigned*>(&hi);
            g_X0h[(size_t)r * 32 + tx] = p;
            if (r >= g)
                out4[(size_t)(N + r - g) * 32 + tx] = v;
        }
    }
}

// ---------------------------------------------------------------------------
// CSR build (identical to R3)
// ---------------------------------------------------------------------------
__global__ void hist_kernel(const int* __restrict__ esrc, int E) {
    for (int e = blockIdx.x * blockDim.x + threadIdx.x; e < E;
         e += gridDim.x * blockDim.x)
        atomicAdd(&g_cnt[esrc[e]], 1);
}

__global__ __launch_bounds__(256) void scan1_kernel(int N) {
    __shared__ int ssum[256];
    const int t = threadIdx.x;
    const int base = blockIdx.x * SCAN_BLK + t * 4;

    int c0 = 0, c1 = 0, c2 = 0, c3 = 0;
    if (base + 0 < N) { c0 = g_cnt[base + 0]; g_cnt[base + 0] = 0; }
    if (base + 1 < N) { c1 = g_cnt[base + 1]; g_cnt[base + 1] = 0; }
    if (base + 2 < N) { c2 = g_cnt[base + 2]; g_cnt[base + 2] = 0; }
    if (base + 3 < N) { c3 = g_cnt[base + 3]; g_cnt[base + 3] = 0; }
    int tot = c0 + c1 + c2 + c3;

    ssum[t] = tot;
    __syncthreads();
    #pragma unroll
    for (int off = 1; off < 256; off <<= 1) {
        int v = (t >= off) ? ssum[t - off] : 0;
        __syncthreads();
        ssum[t] += v;
        __syncthreads();
    }
    int ex = ssum[t] - tot;

    if (base + 0 < N) g_off[base + 0] = ex;
    if (base + 1 < N) g_off[base + 1] = ex + c0;
    if (base + 2 < N) g_off[base + 2] = ex + c0 + c1;
    if (base + 3 < N) g_off[base + 3] = ex + c0 + c1 + c2;
    if (t == 255) g_blk[blockIdx.x] = ssum[255];
}

__global__ __launch_bounds__(256) void scan2_kernel(int NB) {
    __shared__ int ssum[256];
    const int t = threadIdx.x;
    int v0 = (t < NB) ? g_blk[t] : 0;
    ssum[t] = v0;
    __syncthreads();
    #pragma unroll
    for (int off = 1; off < 256; off <<= 1) {
        int v = (t >= off) ? ssum[t - off] : 0;
        __syncthreads();
        ssum[t] += v;
        __syncthreads();
    }
    if (t < NB) g_blk[t] = ssum[t] - v0;   // in-place exclusive block offsets
}

__global__ void scan3_kernel(int N, int E) {
    int i = blockIdx.x * blockDim.x + threadIdx.x;
    if (i < N) {
        int v = g_off[i] + g_blk[i / SCAN_BLK];
        g_off[i] = v;
        g_cur[i] = v;
    }
    if (i == 0) g_off[N] = E;
}

__global__ void scatter_kernel(const int* __restrict__ esrc,
                               const int* __restrict__ edst,
                               const float* __restrict__ ew, int E) {
    for (int e = blockIdx.x * blockDim.x + threadIdx.x; e < E;
         e += gridDim.x * blockDim.x) {
        int s = esrc[e];
        int p = atomicAdd(&g_cur[s], 1);
        g_sdw[p] = make_int2(edst[e], __float_as_int(ew[e]));
    }
}

// ---------------------------------------------------------------------------
// Gather (identical to R3): warp per node, staged lane-load + shuffles,
// fp32 accumulate, fused bias+relu -> out head.
// ---------------------------------------------------------------------------
__global__ __launch_bounds__(256) void gather_kernel(
    const float4* __restrict__ b4,
    float4* __restrict__ out4,
    int N)
{
    const int lane = threadIdx.x & 31;
    const int node = (blockIdx.x * blockDim.x + threadIdx.x) >> 5;
    if (node >= N) return;

    const int start = g_off[node];
    const int end   = g_off[node + 1];

    float4 acc = make_float4(0.f, 0.f, 0.f, 0.f);

    for (int j = start; j < end; j += 32) {
        const int m = min(32, end - j);
        int   dv = 0;
        float wv = 0.f;
        if (lane < m) {
            int2 p = g_sdw[j + lane];
            dv = p.x;
            wv = __int_as_float(p.y);
        }
        int k = 0;
        for (; k + 4 <= m; k += 4) {
            int   d0 = __shfl_sync(0xffffffffu, dv, k + 0);
            int   d1 = __shfl_sync(0xffffffffu, dv, k + 1);
            int   d2 = __shfl_sync(0xffffffffu, dv, k + 2);
            int   d3 = __shfl_sync(0xffffffffu, dv, k + 3);
            float w0 = __shfl_sync(0xffffffffu, wv, k + 0);
            float w1 = __shfl_sync(0xffffffffu, wv, k + 1);
            float w2 = __shfl_sync(0xffffffffu, wv, k + 2);
            float w3 = __shfl_sync(0xffffffffu, wv, k + 3);
            uint2 u0 = g_X0h[(size_t)d0 * 32 + lane];
            uint2 u1 = g_X0h[(size_t)d1 * 32 + lane];
            uint2 u2 = g_X0h[(size_t)d2 * 32 + lane];
            uint2 u3 = g_X0h[(size_t)d3 * 32 + lane];
            float2 a0 = __half22float2(*reinterpret_cast<__half2*>(&u0.x));
            float2 b0 = __half22float2(*reinterpret_cast<__half2*>(&u0.y));
            float2 a1 = __half22float2(*reinterpret_cast<__half2*>(&u1.x));
            float2 b1 = __half22float2(*reinterpret_cast<__half2*>(&u1.y));
            float2 a2 = __half22float2(*reinterpret_cast<__half2*>(&u2.x));
            float2 b2 = __half22float2(*reinterpret_cast<__half2*>(&u2.y));
            float2 a3 = __half22float2(*reinterpret_cast<__half2*>(&u3.x));
            float2 b3 = __half22float2(*reinterpret_cast<__half2*>(&u3.y));
            acc.x += w0 * a0.x + w1 * a1.x + w2 * a2.x + w3 * a3.x;
            acc.y += w0 * a0.y + w1 * a1.y + w2 * a2.y + w3 * a3.y;
            acc.z += w0 * b0.x + w1 * b1.x + w2 * b2.x + w3 * b3.x;
            acc.w += w0 * b0.y + w1 * b1.y + w2 * b2.y + w3 * b3.y;
        }
        for (; k < m; k++) {
            int   d = __shfl_sync(0xffffffffu, dv, k);
            float w = __shfl_sync(0xffffffffu, wv, k);
            uint2 u = g_X0h[(size_t)d * 32 + lane];
            float2 a = __half22float2(*reinterpret_cast<__half2*>(&u.x));
            float2 c = __half22float2(*reinterpret_cast<__half2*>(&u.y));
            acc.x += w * a.x;
            acc.y += w * a.y;
            acc.z += w * c.x;
            acc.w += w * c.y;
        }
    }

    float4 bb = __ldg(b4 + lane);
    acc.x = fmaxf(acc.x + bb.x, 0.f);
    acc.y = fmaxf(acc.y + bb.y, 0.f);
    acc.z = fmaxf(acc.z + bb.z, 0.f);
    acc.w = fmaxf(acc.w + bb.w, 0.f);
    out4[(size_t)node * 32 + lane] = acc;
}

// ---------------------------------------------------------------------------
extern "C" void kernel_launch(void* const* d_in, const int* in_sizes, int n_in,
                              void* d_out, int out_size)
{
    const float* notes = (const float*)d_in[0];
    const float* w     = (const float*)d_in[1];
    const float* b     = (const float*)d_in[2];
    const int*   esrc  = (const int*)  d_in[3];
    const int*   edst  = (const int*)  d_in[4];
    const float* ew    = (const float*)d_in[5];

    const int H = in_sizes[2];
    const int D = in_sizes[1] / H;
    const int N = in_sizes[0] / D;
    const int E = in_sizes[3];
    const int g = 2 * N - out_size / H;

    float4* out4 = (float4*)d_out;
    const int NB = (N + SCAN_BLK - 1) / SCAN_BLK;

    wprep_kernel<<<1, 256>>>(w);
    hist_kernel<<<592, 256>>>(esrc, E);
    scan1_kernel<<<NB, 256>>>(N);
    scan2_kernel<<<1, 256>>>(NB);
    scan3_kernel<<<(N + 255) / 256, 256>>>(N, E);
    scatter_kernel<<<592, 256>>>(esrc, edst, ew, E);

    gemm_kernel<<<(N + BM - 1) / BM, 256>>>(
        (const float4*)notes, out4, N, g);

    gather_kernel<<<(N * 32 + 255) / 256, 256>>>(
        (const float4*)b, out4, N);
}

// round 6
// speedup vs baseline: 1.7358x; 1.7139x over previous
#include <cuda_runtime.h>
#include <cuda_fp16.h>
#include <cuda_bf16.h>
#include <mma.h>

using namespace nvcuda;

// ---------------------------------------------------------------------------
// PhysicsConvolution: X0 = notes@w ; X1 = segment_sum(ew * X0[dst], src) ;
// out = concat(relu(X1 + b), X0[garment:])
//
// R6 = R3 structure + split-fp16 HMMA GEMM with smem-staged W (hi+lo) and
// conflict-free padded fragment layout (ld=136).  X0 = Ah@Wh+Ah@Wl+Al@Wh,
// fp32 accumulate -> ~fp32-accurate X0.
// ---------------------------------------------------------------------------

#define HD   128
#define BM   64
#define PAD  136                 // fragment row stride in halves (272B: conflict-free)

#define MAXN 131072
#define MAXE 1700000
#define SCAN_BLK 1024

// dynamic smem: Wh[128*136] Wl[128*136] Ah[64*136] Al[64*136] (halves);
// C (fp32 64x128) aliases the A region.
#define SMEM_BYTES ((2 * HD * PAD + 2 * BM * PAD) * 2)

__device__ uint2  g_X0h[3400000];       // fp16 X0: [N][32] x 4 halves
__device__ int2   g_sdw[MAXE];          // CSR payload {dst, w}
__device__ int    g_cnt[MAXN + 1];      // zero at load; scan1 restores zeros
__device__ int    g_off[MAXN + 2];
__device__ int    g_cur[MAXN + 1];
__device__ int    g_blk[256];
__device__ __half g_Wh[HD * HD];        // W split: hi fp16
__device__ __half g_Wl[HD * HD];        // W split: lo residual fp16

// ---------------------------------------------------------------------------
// W split prep: Wh = fp16(w), Wl = fp16(w - Wh).
// ---------------------------------------------------------------------------
__global__ void wprep_kernel(const float* __restrict__ w) {
    int i = blockIdx.x * blockDim.x + threadIdx.x;
    if (i < HD * HD) {
        float  v  = w[i];
        __half hi = __float2half_rn(v);
        __half lo = __float2half_rn(v - __half2float(hi));
        g_Wh[i] = hi;
        g_Wl[i] = lo;
    }
}

// ---------------------------------------------------------------------------
// GEMM via split-fp16 HMMA, all operands staged in smem.
// Block: 256 thr = 8 warps; tile 64 rows x 128 cols.
// Warp (wr = wid/2, wc = wid%2): rows wr*16..+15, cols wc*64..+63.
// ---------------------------------------------------------------------------
__global__ __launch_bounds__(256) void gemm_kernel(
    const float4* __restrict__ A4,
    float4* __restrict__ out4,
    int N, int g)
{
    extern __shared__ char smem[];
    __half* sWh = reinterpret_cast<__half*>(smem);        // HD x PAD
    __half* sWl = sWh + HD * PAD;                         // HD x PAD
    __half* sAh = sWl + HD * PAD;                         // BM x PAD
    __half* sAl = sAh + BM * PAD;                         // BM x PAD
    float*  sC  = reinterpret_cast<float*>(sAh);          // BM x HD (aliases A)

    const int tid  = threadIdx.x;
    const int row0 = blockIdx.x * BM;

    // Stage W (hi+lo) into smem: coalesced 4-half chunks.
    #pragma unroll
    for (int i = tid; i < HD * 32; i += 256) {            // 4096 uint2 chunks
        int row = i >> 5, c4 = (i & 31) * 4;
        uint2 h = reinterpret_cast<const uint2*>(g_Wh)[i];
        uint2 l = reinterpret_cast<const uint2*>(g_Wl)[i];
        *reinterpret_cast<uint2*>(sWh + row * PAD + c4) = h;
        *reinterpret_cast<uint2*>(sWl + row * PAD + c4) = l;
    }

    // Load A tile (fp32) and split into (hi, lo) fp16 in smem.
    #pragma unroll
    for (int i = tid; i < BM * 32; i += 256) {
        int rl = i >> 5, c4 = (i & 31) * 4;
        int r  = row0 + rl;
        float4 a = (r < N) ? A4[(size_t)r * 32 + (i & 31)]
                           : make_float4(0.f, 0.f, 0.f, 0.f);
        __half hv[4], lv[4];
        #pragma unroll
        for (int u = 0; u < 4; u++) {
            float  v  = (&a.x)[u];
            __half hi = __float2half_rn(v);
            hv[u] = hi;
            lv[u] = __float2half_rn(v - __half2float(hi));
        }
        *reinterpret_cast<uint2*>(sAh + rl * PAD + c4) =
            *reinterpret_cast<uint2*>(hv);
        *reinterpret_cast<uint2*>(sAl + rl * PAD + c4) =
            *reinterpret_cast<uint2*>(lv);
    }
    __syncthreads();

    const int wid = tid >> 5;
    const int wr  = wid >> 1;
    const int wc  = wid & 1;

    wmma::fragment<wmma::accumulator, 16, 16, 16, float> acc[4];
    #pragma unroll
    for (int j = 0; j < 4; j++) wmma::fill_fragment(acc[j], 0.f);

    #pragma unroll
    for (int k = 0; k < 8; k++) {
        const int k0 = k * 16;
        wmma::fragment<wmma::matrix_a, 16, 16, 16, __half, wmma::row_major> ah, al;
        wmma::load_matrix_sync(ah, sAh + (wr * 16) * PAD + k0, PAD);
        wmma::load_matrix_sync(al, sAl + (wr * 16) * PAD + k0, PAD);
        #pragma unroll
        for (int j = 0; j < 4; j++) {
            const int col = wc * 64 + j * 16;
            wmma::fragment<wmma::matrix_b, 16, 16, 16, __half, wmma::row_major> bh, bl;
            wmma::load_matrix_sync(bh, sWh + k0 * PAD + col, PAD);
            wmma::load_matrix_sync(bl, sWl + k0 * PAD + col, PAD);
            wmma::mma_sync(acc[j], ah, bh, acc[j]);
            wmma::mma_sync(acc[j], ah, bl, acc[j]);
            wmma::mma_sync(acc[j], al, bh, acc[j]);
        }
    }

    __syncthreads();   // done reading A region; reuse as fp32 C
    #pragma unroll
    for (int j = 0; j < 4; j++)
        wmma::store_matrix_sync(sC + (wr * 16) * HD + wc * 64 + j * 16,
                                acc[j], HD, wmma::mem_row_major);
    __syncthreads();

    // Pack: fp16 X0 for gather, fp32 tail rows for out.
    const int tx = tid & 31;
    const int ty = tid >> 5;
    #pragma unroll
    for (int i = 0; i < 8; i++) {
        int rl = ty * 8 + i;
        int r  = row0 + rl;
        if (r < N) {
            float4 v = *reinterpret_cast<float4*>(sC + rl * HD + tx * 4);
            __half2 lo = __float22half2_rn(make_float2(v.x, v.y));
            __half2 hi = __float22half2_rn(make_float2(v.z, v.w));
            uint2 p;
            p.x = *reinterpret_cast<unsigned*>(&lo);
            p.y = *reinterpret_cast<unsigned*>(&hi);
            g_X0h[(size_t)r * 32 + tx] = p;
            if (r >= g)
                out4[(size_t)(N + r - g) * 32 + tx] = v;
        }
    }
}

// ---------------------------------------------------------------------------
// CSR build (identical to R3/R5)
// ---------------------------------------------------------------------------
__global__ void hist_kernel(const int* __restrict__ esrc, int E) {
    for (int e = blockIdx.x * blockDim.x + threadIdx.x; e < E;
         e += gridDim.x * blockDim.x)
        atomicAdd(&g_cnt[esrc[e]], 1);
}

__global__ __launch_bounds__(256) void scan1_kernel(int N) {
    __shared__ int ssum[256];
    const int t = threadIdx.x;
    const int base = blockIdx.x * SCAN_BLK + t * 4;

    int c0 = 0, c1 = 0, c2 = 0, c3 = 0;
    if (base + 0 < N) { c0 = g_cnt[base + 0]; g_cnt[base + 0] = 0; }
    if (base + 1 < N) { c1 = g_cnt[base + 1]; g_cnt[base + 1] = 0; }
    if (base + 2 < N) { c2 = g_cnt[base + 2]; g_cnt[base + 2] = 0; }
    if (base + 3 < N) { c3 = g_cnt[base + 3]; g_cnt[base + 3] = 0; }
    int tot = c0 + c1 + c2 + c3;

    ssum[t] = tot;
    __syncthreads();
    #pragma unroll
    for (int off = 1; off < 256; off <<= 1) {
        int v = (t >= off) ? ssum[t - off] : 0;
        __syncthreads();
        ssum[t] += v;
        __syncthreads();
    }
    int ex = ssum[t] - tot;

    if (base + 0 < N) g_off[base + 0] = ex;
    if (base + 1 < N) g_off[base + 1] = ex + c0;
    if (base + 2 < N) g_off[base + 2] = ex + c0 + c1;
    if (base + 3 < N) g_off[base + 3] = ex + c0 + c1 + c2;
    if (t == 255) g_blk[blockIdx.x] = ssum[255];
}

__global__ __launch_bounds__(256) void scan2_kernel(int NB) {
    __shared__ int ssum[256];
    const int t = threadIdx.x;
    int v0 = (t < NB) ? g_blk[t] : 0;
    ssum[t] = v0;
    __syncthreads();
    #pragma unroll
    for (int off = 1; off < 256; off <<= 1) {
        int v = (t >= off) ? ssum[t - off] : 0;
        __syncthreads();
        ssum[t] += v;
        __syncthreads();
    }
    if (t < NB) g_blk[t] = ssum[t] - v0;
}

__global__ void scan3_kernel(int N, int E) {
    int i = blockIdx.x * blockDim.x + threadIdx.x;
    if (i < N) {
        int v = g_off[i] + g_blk[i / SCAN_BLK];
        g_off[i] = v;
        g_cur[i] = v;
    }
    if (i == 0) g_off[N] = E;
}

__global__ void scatter_kernel(const int* __restrict__ esrc,
                               const int* __restrict__ edst,
                               const float* __restrict__ ew, int E) {
    for (int e = blockIdx.x * blockDim.x + threadIdx.x; e < E;
         e += gridDim.x * blockDim.x) {
        int s = esrc[e];
        int p = atomicAdd(&g_cur[s], 1);
        g_sdw[p] = make_int2(edst[e], __float_as_int(ew[e]));
    }
}

// ---------------------------------------------------------------------------
// Gather (identical to R3)
// ---------------------------------------------------------------------------
__global__ __launch_bounds__(256) void gather_kernel(
    const float4* __restrict__ b4,
    float4* __restrict__ out4,
    int N)
{
    const int lane = threadIdx.x & 31;
    const int node = (blockIdx.x * blockDim.x + threadIdx.x) >> 5;
    if (node >= N) return;

    const int start = g_off[node];
    const int end   = g_off[node + 1];

    float4 acc = make_float4(0.f, 0.f, 0.f, 0.f);

    for (int j = start; j < end; j += 32) {
        const int m = min(32, end - j);
        int   dv = 0;
        float wv = 0.f;
        if (lane < m) {
            int2 p = g_sdw[j + lane];
            dv = p.x;
            wv = __int_as_float(p.y);
        }
        int k = 0;
        for (; k + 4 <= m; k += 4) {
            int   d0 = __shfl_sync(0xffffffffu, dv, k + 0);
            int   d1 = __shfl_sync(0xffffffffu, dv, k + 1);
            int   d2 = __shfl_sync(0xffffffffu, dv, k + 2);
            int   d3 = __shfl_sync(0xffffffffu, dv, k + 3);
            float w0 = __shfl_sync(0xffffffffu, wv, k + 0);
            float w1 = __shfl_sync(0xffffffffu, wv, k + 1);
            float w2 = __shfl_sync(0xffffffffu, wv, k + 2);
            float w3 = __shfl_sync(0xffffffffu, wv, k + 3);
            uint2 u0 = g_X0h[(size_t)d0 * 32 + lane];
            uint2 u1 = g_X0h[(size_t)d1 * 32 + lane];
            uint2 u2 = g_X0h[(size_t)d2 * 32 + lane];
            uint2 u3 = g_X0h[(size_t)d3 * 32 + lane];
            float2 a0 = __half22float2(*reinterpret_cast<__half2*>(&u0.x));
            float2 b0 = __half22float2(*reinterpret_cast<__half2*>(&u0.y));
            float2 a1 = __half22float2(*reinterpret_cast<__half2*>(&u1.x));
            float2 b1 = __half22float2(*reinterpret_cast<__half2*>(&u1.y));
            float2 a2 = __half22float2(*reinterpret_cast<__half2*>(&u2.x));
            float2 b2 = __half22float2(*reinterpret_cast<__half2*>(&u2.y));
            float2 a3 = __half22float2(*reinterpret_cast<__half2*>(&u3.x));
            float2 b3 = __half22float2(*reinterpret_cast<__half2*>(&u3.y));
            acc.x += w0 * a0.x + w1 * a1.x + w2 * a2.x + w3 * a3.x;
            acc.y += w0 * a0.y + w1 * a1.y + w2 * a2.y + w3 * a3.y;
            acc.z += w0 * b0.x + w1 * b1.x + w2 * b2.x + w3 * b3.x;
            acc.w += w0 * b0.y + w1 * b1.y + w2 * b2.y + w3 * b3.y;
        }
        for (; k < m; k++) {
            int   d = __shfl_sync(0xffffffffu, dv, k);
            float w = __shfl_sync(0xffffffffu, wv, k);
            uint2 u = g_X0h[(size_t)d * 32 + lane];
            float2 a = __half22float2(*reinterpret_cast<__half2*>(&u.x));
            float2 c = __half22float2(*reinterpret_cast<__half2*>(&u.y));
            acc.x += w * a.x;
            acc.y += w * a.y;
            acc.z += w * c.x;
            acc.w += w * c.y;
        }
    }

    float4 bb = __ldg(b4 + lane);
    acc.x = fmaxf(acc.x + bb.x, 0.f);
    acc.y = fmaxf(acc.y + bb.y, 0.f);
    acc.z = fmaxf(acc.z + bb.z, 0.f);
    acc.w = fmaxf(acc.w + bb.w, 0.f);
    out4[(size_t)node * 32 + lane] = acc;
}

// ---------------------------------------------------------------------------
extern "C" void kernel_launch(void* const* d_in, const int* in_sizes, int n_in,
                              void* d_out, int out_size)
{
    const float* notes = (const float*)d_in[0];
    const float* w     = (const float*)d_in[1];
    const float* b     = (const float*)d_in[2];
    const int*   esrc  = (const int*)  d_in[3];
    const int*   edst  = (const int*)  d_in[4];
    const float* ew    = (const float*)d_in[5];

    const int H = in_sizes[2];
    const int D = in_sizes[1] / H;
    const int N = in_sizes[0] / D;
    const int E = in_sizes[3];
    const int g = 2 * N - out_size / H;

    float4* out4 = (float4*)d_out;
    const int NB = (N + SCAN_BLK - 1) / SCAN_BLK;

    cudaFuncSetAttribute(gemm_kernel,
                         cudaFuncAttributeMaxDynamicSharedMemorySize,
                         SMEM_BYTES);

    wprep_kernel<<<HD * HD / 256, 256>>>(w);
    hist_kernel<<<592, 256>>>(esrc, E);
    scan1_kernel<<<NB, 256>>>(N);
    scan2_kernel<<<1, 256>>>(NB);
    scan3_kernel<<<(N + 255) / 256, 256>>>(N, E);
    scatter_kernel<<<592, 256>>>(esrc, edst, ew, E);

    gemm_kernel<<<(N + BM - 1) / BM, 256, SMEM_BYTES>>>(
        (const float4*)notes, out4, N, g);

    gather_kernel<<<(N * 32 + 255) / 256, 256>>>(
        (const float4*)b, out4, N);
}